// round 3
// baseline (speedup 1.0000x reference)
#include <cuda_runtime.h>
#include <cstddef>

#define N_SRC   16384
#define N_TGT   65536
#define KNBR    8
#define CCH     16
#define CSKIP   2
#define SSC     32
#define HID     64
#define MVD     16
#define ROW_MV  (CCH*MVD)
#define TPB     64
#define TGT_PER_BLOCK 16
#define MV_STRIDE 304     // mod 32 = 16 -> warp halves (dtl=1) hit disjoint banks
#define SC_STRIDE 68

__device__ float g_Weff[(CCH + CSKIP) * CCH];

// ---------------------------------------------------------------------------
__global__ void prep_weff(const float* __restrict__ W1_mv,
                          const float* __restrict__ W2_mv)
{
    int idx = threadIdx.x;
    if (idx < (CCH + CSKIP) * CCH) {
        int cp = idx >> 4;
        int c  = idx & 15;
        float acc = 0.f;
        #pragma unroll
        for (int h = 0; h < HID; h++)
            acc = fmaf(W1_mv[cp * HID + h], W2_mv[h * CCH + c], acc);
        g_Weff[idx] = acc;
    }
}

__device__ __forceinline__ float gelu_tanh(float x)
{
    const float c0 = 0.7978845608028654f;
    float u = c0 * fmaf(0.044715f * x, x * x, x);
    float t = tanhf(u);
    return 0.5f * x * (1.0f + t);
}

// ---------------------------------------------------------------------------
__global__ __launch_bounds__(TPB) void fused_kernel(
    const float* __restrict__ mv_src,  const float* __restrict__ mv_skip,
    const float* __restrict__ sc_src,  const float* __restrict__ sc_skip,
    const float* __restrict__ pos_src, const float* __restrict__ pos_tgt,
    const int*   __restrict__ isrc,
    const float* __restrict__ W1_s,    const float* __restrict__ b1_s,
    const float* __restrict__ W2_s,    const float* __restrict__ b2_s,
    float* __restrict__ out_mv,        float* __restrict__ out_sc)
{
    __shared__ __align__(16) float sMV[TGT_PER_BLOCK * MV_STRIDE];  // 19.0 KB
    __shared__ __align__(16) float sSC[TGT_PER_BLOCK * SC_STRIDE];  // 4.25 KB (x, then h in-place)

    const int tid  = threadIdx.x;
    const int lane = tid & 31;
    const int warp = tid >> 5;               // 0..1
    const int tbase = blockIdx.x * TGT_PER_BLOCK;

    // ---------------- Phase 1: IDW interpolation (warp per target, x8) ------
    #pragma unroll
    for (int u = 0; u < 8; u++) {
        const int tl = warp * 8 + u;
        const int t  = tbase + tl;

        float wk = 0.f;
        int   sk = 0;
        if (lane < KNBR) {
            sk = isrc[t * KNBR + lane];
            float dx = pos_src[sk * 3 + 0] - pos_tgt[t * 3 + 0];
            float dy = pos_src[sk * 3 + 1] - pos_tgt[t * 3 + 1];
            float dz = pos_src[sk * 3 + 2] - pos_tgt[t * 3 + 2];
            float d2 = fmaf(dx, dx, fmaf(dy, dy, dz * dz));
            d2 = fmaxf(d2, 1e-16f);
            wk = 1.0f / d2;
        }
        float den = wk;
        #pragma unroll
        for (int o = 16; o; o >>= 1) den += __shfl_xor_sync(0xffffffffu, den, o);
        const float invd = 1.0f / den;

        float4 a0 = make_float4(0.f, 0.f, 0.f, 0.f);
        float4 a1 = make_float4(0.f, 0.f, 0.f, 0.f);
        float  sacc = 0.f;
        #pragma unroll
        for (int k = 0; k < KNBR; k++) {
            const float w = __shfl_sync(0xffffffffu, wk, k);
            const int   s = __shfl_sync(0xffffffffu, sk, k);
            const float4* row = (const float4*)(mv_src + (size_t)s * ROW_MV);
            float4 v0 = __ldg(row + lane);
            float4 v1 = __ldg(row + lane + 32);
            a0.x = fmaf(w, v0.x, a0.x); a0.y = fmaf(w, v0.y, a0.y);
            a0.z = fmaf(w, v0.z, a0.z); a0.w = fmaf(w, v0.w, a0.w);
            a1.x = fmaf(w, v1.x, a1.x); a1.y = fmaf(w, v1.y, a1.y);
            a1.z = fmaf(w, v1.z, a1.z); a1.w = fmaf(w, v1.w, a1.w);
            sacc = fmaf(w, __ldg(sc_src + (size_t)s * SSC + lane), sacc);
        }
        a0.x *= invd; a0.y *= invd; a0.z *= invd; a0.w *= invd;
        a1.x *= invd; a1.y *= invd; a1.z *= invd; a1.w *= invd;

        float4* mrow = (float4*)(sMV + tl * MV_STRIDE);
        mrow[lane]      = a0;
        mrow[lane + 32] = a1;
        sMV[tl * MV_STRIDE + 256 + lane] = mv_skip[(size_t)t * (CSKIP * MVD) + lane];
        sSC[tl * SC_STRIDE + lane]       = sacc * invd;
        sSC[tl * SC_STRIDE + 32 + lane]  = sc_skip[(size_t)t * SSC + lane];
    }
    __syncthreads();

    const int g   = tid >> 4;          // 0..3 group; owns targets {g, g+4, g+8, g+12}
    const int sub = tid & 15;

    // ---------------- Phase 2: mv output (fused Weff), 2 passes x 2 targets --
    #pragma unroll
    for (int p2 = 0; p2 < 2; p2++) {
        const int tlA = g + 4 * (2 * p2);
        const int tlB = g + 4 * (2 * p2 + 1);
        const int i = sub;
        const float* mA = sMV + tlA * MV_STRIDE + i;
        const float* mB = sMV + tlB * MV_STRIDE + i;
        float oa[16], ob[16];
        #pragma unroll
        for (int c = 0; c < 16; c++) { oa[c] = 0.f; ob[c] = 0.f; }
        #pragma unroll
        for (int cp = 0; cp < CCH + CSKIP; cp++) {
            const float ma = mA[cp * 16];
            const float mb = mB[cp * 16];
            const float4* wr = (const float4*)(g_Weff + cp * 16);
            float4 w0 = __ldg(wr), w1 = __ldg(wr + 1), w2 = __ldg(wr + 2), w3 = __ldg(wr + 3);
            oa[0]  = fmaf(ma, w0.x, oa[0]);  ob[0]  = fmaf(mb, w0.x, ob[0]);
            oa[1]  = fmaf(ma, w0.y, oa[1]);  ob[1]  = fmaf(mb, w0.y, ob[1]);
            oa[2]  = fmaf(ma, w0.z, oa[2]);  ob[2]  = fmaf(mb, w0.z, ob[2]);
            oa[3]  = fmaf(ma, w0.w, oa[3]);  ob[3]  = fmaf(mb, w0.w, ob[3]);
            oa[4]  = fmaf(ma, w1.x, oa[4]);  ob[4]  = fmaf(mb, w1.x, ob[4]);
            oa[5]  = fmaf(ma, w1.y, oa[5]);  ob[5]  = fmaf(mb, w1.y, ob[5]);
            oa[6]  = fmaf(ma, w1.z, oa[6]);  ob[6]  = fmaf(mb, w1.z, ob[6]);
            oa[7]  = fmaf(ma, w1.w, oa[7]);  ob[7]  = fmaf(mb, w1.w, ob[7]);
            oa[8]  = fmaf(ma, w2.x, oa[8]);  ob[8]  = fmaf(mb, w2.x, ob[8]);
            oa[9]  = fmaf(ma, w2.y, oa[9]);  ob[9]  = fmaf(mb, w2.y, ob[9]);
            oa[10] = fmaf(ma, w2.z, oa[10]); ob[10] = fmaf(mb, w2.z, ob[10]);
            oa[11] = fmaf(ma, w2.w, oa[11]); ob[11] = fmaf(mb, w2.w, ob[11]);
            oa[12] = fmaf(ma, w3.x, oa[12]); ob[12] = fmaf(mb, w3.x, ob[12]);
            oa[13] = fmaf(ma, w3.y, oa[13]); ob[13] = fmaf(mb, w3.y, ob[13]);
            oa[14] = fmaf(ma, w3.z, oa[14]); ob[14] = fmaf(mb, w3.z, ob[14]);
            oa[15] = fmaf(ma, w3.w, oa[15]); ob[15] = fmaf(mb, w3.w, ob[15]);
        }
        float* dA = out_mv + (size_t)(tbase + tlA) * ROW_MV + i;
        float* dB = out_mv + (size_t)(tbase + tlB) * ROW_MV + i;
        #pragma unroll
        for (int c = 0; c < 16; c++) { dA[c * 16] = oa[c]; dB[c * 16] = ob[c]; }
    }

    // ---------------- Phase 3a: scalar hidden + gelu, 4 targets/thread ------
    {
        const int h4 = sub * 4;
        float4 bb = __ldg((const float4*)(b1_s + h4));
        float a0 = bb.x, a1 = bb.y, a2 = bb.z, a3 = bb.w;
        float b0 = bb.x, b1 = bb.y, b2 = bb.z, b3 = bb.w;
        float c0 = bb.x, c1 = bb.y, c2_ = bb.z, c3 = bb.w;
        float d0 = bb.x, d1 = bb.y, d2 = bb.z, d3 = bb.w;
        const float* xA = sSC + (g)      * SC_STRIDE;
        const float* xB = sSC + (g + 4)  * SC_STRIDE;
        const float* xC = sSC + (g + 8)  * SC_STRIDE;
        const float* xD = sSC + (g + 12) * SC_STRIDE;
        #pragma unroll
        for (int jc = 0; jc < 16; jc++) {
            float4 xa = *(const float4*)(xA + 4 * jc);
            float4 xb = *(const float4*)(xB + 4 * jc);
            float4 xc = *(const float4*)(xC + 4 * jc);
            float4 xd = *(const float4*)(xD + 4 * jc);
            const float* wb = W1_s + (4 * jc) * HID + h4;
            float4 w0 = __ldg((const float4*)(wb));
            float4 w1 = __ldg((const float4*)(wb + HID));
            float4 w2 = __ldg((const float4*)(wb + 2 * HID));
            float4 w3 = __ldg((const float4*)(wb + 3 * HID));

            a0 = fmaf(xa.x, w0.x, a0); a1 = fmaf(xa.x, w0.y, a1); a2 = fmaf(xa.x, w0.z, a2); a3 = fmaf(xa.x, w0.w, a3);
            b0 = fmaf(xb.x, w0.x, b0); b1 = fmaf(xb.x, w0.y, b1); b2 = fmaf(xb.x, w0.z, b2); b3 = fmaf(xb.x, w0.w, b3);
            c0 = fmaf(xc.x, w0.x, c0); c1 = fmaf(xc.x, w0.y, c1); c2_ = fmaf(xc.x, w0.z, c2_); c3 = fmaf(xc.x, w0.w, c3);
            d0 = fmaf(xd.x, w0.x, d0); d1 = fmaf(xd.x, w0.y, d1); d2 = fmaf(xd.x, w0.z, d2); d3 = fmaf(xd.x, w0.w, d3);

            a0 = fmaf(xa.y, w1.x, a0); a1 = fmaf(xa.y, w1.y, a1); a2 = fmaf(xa.y, w1.z, a2); a3 = fmaf(xa.y, w1.w, a3);
            b0 = fmaf(xb.y, w1.x, b0); b1 = fmaf(xb.y, w1.y, b1); b2 = fmaf(xb.y, w1.z, b2); b3 = fmaf(xb.y, w1.w, b3);
            c0 = fmaf(xc.y, w1.x, c0); c1 = fmaf(xc.y, w1.y, c1); c2_ = fmaf(xc.y, w1.z, c2_); c3 = fmaf(xc.y, w1.w, c3);
            d0 = fmaf(xd.y, w1.x, d0); d1 = fmaf(xd.y, w1.y, d1); d2 = fmaf(xd.y, w1.z, d2); d3 = fmaf(xd.y, w1.w, d3);

            a0 = fmaf(xa.z, w2.x, a0); a1 = fmaf(xa.z, w2.y, a1); a2 = fmaf(xa.z, w2.z, a2); a3 = fmaf(xa.z, w2.w, a3);
            b0 = fmaf(xb.z, w2.x, b0); b1 = fmaf(xb.z, w2.y, b1); b2 = fmaf(xb.z, w2.z, b2); b3 = fmaf(xb.z, w2.w, b3);
            c0 = fmaf(xc.z, w2.x, c0); c1 = fmaf(xc.z, w2.y, c1); c2_ = fmaf(xc.z, w2.z, c2_); c3 = fmaf(xc.z, w2.w, c3);
            d0 = fmaf(xd.z, w2.x, d0); d1 = fmaf(xd.z, w2.y, d1); d2 = fmaf(xd.z, w2.z, d2); d3 = fmaf(xd.z, w2.w, d3);

            a0 = fmaf(xa.w, w3.x, a0); a1 = fmaf(xa.w, w3.y, a1); a2 = fmaf(xa.w, w3.z, a2); a3 = fmaf(xa.w, w3.w, a3);
            b0 = fmaf(xb.w, w3.x, b0); b1 = fmaf(xb.w, w3.y, b1); b2 = fmaf(xb.w, w3.z, b2); b3 = fmaf(xb.w, w3.w, b3);
            c0 = fmaf(xc.w, w3.x, c0); c1 = fmaf(xc.w, w3.y, c1); c2_ = fmaf(xc.w, w3.z, c2_); c3 = fmaf(xc.w, w3.w, c3);
            d0 = fmaf(xd.w, w3.x, d0); d1 = fmaf(xd.w, w3.y, d1); d2 = fmaf(xd.w, w3.z, d2); d3 = fmaf(xd.w, w3.w, d3);
        }
        __syncwarp();   // all x reads in this warp done before in-place h writes
        *(float4*)(sSC + (g)      * SC_STRIDE + h4) = make_float4(gelu_tanh(a0), gelu_tanh(a1), gelu_tanh(a2), gelu_tanh(a3));
        *(float4*)(sSC + (g + 4)  * SC_STRIDE + h4) = make_float4(gelu_tanh(b0), gelu_tanh(b1), gelu_tanh(b2), gelu_tanh(b3));
        *(float4*)(sSC + (g + 8)  * SC_STRIDE + h4) = make_float4(gelu_tanh(c0), gelu_tanh(c1), gelu_tanh(c2_), gelu_tanh(c3));
        *(float4*)(sSC + (g + 12) * SC_STRIDE + h4) = make_float4(gelu_tanh(d0), gelu_tanh(d1), gelu_tanh(d2), gelu_tanh(d3));
    }
    __syncwarp();

    // ---------------- Phase 3b: scalar output, 4 targets/thread -------------
    {
        const int c2 = sub * 2;
        float2 bb = __ldg((const float2*)(b2_s + c2));
        float a0 = bb.x, a1 = bb.y;
        float b0 = bb.x, b1 = bb.y;
        float c0 = bb.x, c1 = bb.y;
        float d0 = bb.x, d1 = bb.y;
        const float* hA = sSC + (g)      * SC_STRIDE;
        const float* hB = sSC + (g + 4)  * SC_STRIDE;
        const float* hC = sSC + (g + 8)  * SC_STRIDE;
        const float* hD = sSC + (g + 12) * SC_STRIDE;
        #pragma unroll
        for (int hc = 0; hc < 16; hc++) {
            float4 ha = *(const float4*)(hA + 4 * hc);
            float4 hb = *(const float4*)(hB + 4 * hc);
            float4 hcv = *(const float4*)(hC + 4 * hc);
            float4 hd = *(const float4*)(hD + 4 * hc);
            const float* wb = W2_s + (4 * hc) * SSC + c2;
            float2 w0 = __ldg((const float2*)(wb));
            float2 w1 = __ldg((const float2*)(wb + SSC));
            float2 w2 = __ldg((const float2*)(wb + 2 * SSC));
            float2 w3 = __ldg((const float2*)(wb + 3 * SSC));
            a0 = fmaf(ha.x, w0.x, a0);  a1 = fmaf(ha.x, w0.y, a1);
            b0 = fmaf(hb.x, w0.x, b0);  b1 = fmaf(hb.x, w0.y, b1);
            c0 = fmaf(hcv.x, w0.x, c0); c1 = fmaf(hcv.x, w0.y, c1);
            d0 = fmaf(hd.x, w0.x, d0);  d1 = fmaf(hd.x, w0.y, d1);
            a0 = fmaf(ha.y, w1.x, a0);  a1 = fmaf(ha.y, w1.y, a1);
            b0 = fmaf(hb.y, w1.x, b0);  b1 = fmaf(hb.y, w1.y, b1);
            c0 = fmaf(hcv.y, w1.x, c0); c1 = fmaf(hcv.y, w1.y, c1);
            d0 = fmaf(hd.y, w1.x, d0);  d1 = fmaf(hd.y, w1.y, d1);
            a0 = fmaf(ha.z, w2.x, a0);  a1 = fmaf(ha.z, w2.y, a1);
            b0 = fmaf(hb.z, w2.x, b0);  b1 = fmaf(hb.z, w2.y, b1);
            c0 = fmaf(hcv.z, w2.x, c0); c1 = fmaf(hcv.z, w2.y, c1);
            d0 = fmaf(hd.z, w2.x, d0);  d1 = fmaf(hd.z, w2.y, d1);
            a0 = fmaf(ha.w, w3.x, a0);  a1 = fmaf(ha.w, w3.y, a1);
            b0 = fmaf(hb.w, w3.x, b0);  b1 = fmaf(hb.w, w3.y, b1);
            c0 = fmaf(hcv.w, w3.x, c0); c1 = fmaf(hcv.w, w3.y, c1);
            d0 = fmaf(hd.w, w3.x, d0);  d1 = fmaf(hd.w, w3.y, d1);
        }
        *(float2*)(out_sc + (size_t)(tbase + g)      * SSC + c2) = make_float2(a0, a1);
        *(float2*)(out_sc + (size_t)(tbase + g + 4)  * SSC + c2) = make_float2(b0, b1);
        *(float2*)(out_sc + (size_t)(tbase + g + 8)  * SSC + c2) = make_float2(c0, c1);
        *(float2*)(out_sc + (size_t)(tbase + g + 12) * SSC + c2) = make_float2(d0, d1);
    }
}

// ---------------------------------------------------------------------------
extern "C" void kernel_launch(void* const* d_in, const int* in_sizes, int n_in,
                              void* d_out, int out_size)
{
    const float* mv_src   = (const float*)d_in[0];
    const float* mv_skip  = (const float*)d_in[1];
    const float* sc_src   = (const float*)d_in[2];
    const float* sc_skip  = (const float*)d_in[3];
    const float* pos_src  = (const float*)d_in[4];
    const float* pos_tgt  = (const float*)d_in[5];
    const int*   isrc     = (const int*)d_in[6];
    const float* W1_mv    = (const float*)d_in[8];
    const float* W2_mv    = (const float*)d_in[9];
    const float* W1_s     = (const float*)d_in[10];
    const float* b1_s     = (const float*)d_in[11];
    const float* W2_s     = (const float*)d_in[12];
    const float* b2_s     = (const float*)d_in[13];

    float* out_mv = (float*)d_out;
    float* out_sc = out_mv + (size_t)N_TGT * CCH * MVD;

    prep_weff<<<1, 288>>>(W1_mv, W2_mv);
    fused_kernel<<<N_TGT / TGT_PER_BLOCK, TPB>>>(
        mv_src, mv_skip, sc_src, sc_skip, pos_src, pos_tgt, isrc,
        W1_s, b1_s, W2_s, b2_s, out_mv, out_sc);
}

// round 4
// speedup vs baseline: 1.0592x; 1.0592x over previous
#include <cuda_runtime.h>
#include <cstddef>

#define N_SRC   16384
#define N_TGT   65536
#define KNBR    8
#define CCH     16
#define CSKIP   2
#define SSC     32
#define HID     64
#define MVD     16
#define ROW_MV  (CCH*MVD)
#define TPB     128
#define TGT_PER_BLOCK 16
#define MV_STRIDE 296     // ≡8 (mod 32): rows r / r+2 differ by 16 banks -> phase-2 conflict-free
#define SC_STRIDE 68

__device__ float g_Weff[(CCH + CSKIP) * CCH];

// ---------------------------------------------------------------------------
__global__ void prep_weff(const float* __restrict__ W1_mv,
                          const float* __restrict__ W2_mv)
{
    int idx = threadIdx.x;
    if (idx < (CCH + CSKIP) * CCH) {
        int cp = idx >> 4;
        int c  = idx & 15;
        float acc = 0.f;
        #pragma unroll
        for (int h = 0; h < HID; h++)
            acc = fmaf(W1_mv[cp * HID + h], W2_mv[h * CCH + c], acc);
        g_Weff[idx] = acc;
    }
}

__device__ __forceinline__ float gelu_tanh(float x)
{
    const float c0 = 0.7978845608028654f;
    float u = c0 * fmaf(0.044715f * x, x * x, x);
    float t = tanhf(u);
    return 0.5f * x * (1.0f + t);
}

// ---------------------------------------------------------------------------
// Warp-private pipeline: warp w owns targets {4w .. 4w+3}; no __syncthreads.
// ---------------------------------------------------------------------------
__global__ __launch_bounds__(TPB, 5) void fused_kernel(
    const float* __restrict__ mv_src,  const float* __restrict__ mv_skip,
    const float* __restrict__ sc_src,  const float* __restrict__ sc_skip,
    const float* __restrict__ pos_src, const float* __restrict__ pos_tgt,
    const int*   __restrict__ isrc,
    const float* __restrict__ W1_s,    const float* __restrict__ b1_s,
    const float* __restrict__ W2_s,    const float* __restrict__ b2_s,
    float* __restrict__ out_mv,        float* __restrict__ out_sc)
{
    __shared__ __align__(16) float sMV[TGT_PER_BLOCK * MV_STRIDE];  // 18.5 KB
    __shared__ __align__(16) float sSC[TGT_PER_BLOCK * SC_STRIDE];  // 4.25 KB (x, then h in-place)

    const int tid  = threadIdx.x;
    const int lane = tid & 31;
    const int warp = tid >> 5;               // 0..3, owns rows 4w..4w+3
    const int tbase = blockIdx.x * TGT_PER_BLOCK;

    // ---------------- Phase 1: IDW interpolation (warp per target, x4) ------
    #pragma unroll
    for (int u = 0; u < 4; u++) {
        const int tl = warp * 4 + u;
        const int t  = tbase + tl;

        float wk = 0.f;
        int   sk = 0;
        if (lane < KNBR) {
            sk = isrc[t * KNBR + lane];
            float dx = pos_src[sk * 3 + 0] - pos_tgt[t * 3 + 0];
            float dy = pos_src[sk * 3 + 1] - pos_tgt[t * 3 + 1];
            float dz = pos_src[sk * 3 + 2] - pos_tgt[t * 3 + 2];
            float d2 = fmaf(dx, dx, fmaf(dy, dy, dz * dz));
            d2 = fmaxf(d2, 1e-16f);
            wk = 1.0f / d2;
        }
        float den = wk;
        #pragma unroll
        for (int o = 16; o; o >>= 1) den += __shfl_xor_sync(0xffffffffu, den, o);
        const float invd = 1.0f / den;

        float4 a0 = make_float4(0.f, 0.f, 0.f, 0.f);
        float4 a1 = make_float4(0.f, 0.f, 0.f, 0.f);
        float  sacc = 0.f;
        #pragma unroll
        for (int k = 0; k < KNBR; k++) {
            const float w = __shfl_sync(0xffffffffu, wk, k);
            const int   s = __shfl_sync(0xffffffffu, sk, k);
            const float4* row = (const float4*)(mv_src + (size_t)s * ROW_MV);
            float4 v0 = __ldg(row + lane);
            float4 v1 = __ldg(row + lane + 32);
            a0.x = fmaf(w, v0.x, a0.x); a0.y = fmaf(w, v0.y, a0.y);
            a0.z = fmaf(w, v0.z, a0.z); a0.w = fmaf(w, v0.w, a0.w);
            a1.x = fmaf(w, v1.x, a1.x); a1.y = fmaf(w, v1.y, a1.y);
            a1.z = fmaf(w, v1.z, a1.z); a1.w = fmaf(w, v1.w, a1.w);
            sacc = fmaf(w, __ldg(sc_src + (size_t)s * SSC + lane), sacc);
        }
        a0.x *= invd; a0.y *= invd; a0.z *= invd; a0.w *= invd;
        a1.x *= invd; a1.y *= invd; a1.z *= invd; a1.w *= invd;

        float4* mrow = (float4*)(sMV + tl * MV_STRIDE);
        mrow[lane]      = a0;
        mrow[lane + 32] = a1;
        sMV[tl * MV_STRIDE + 256 + lane] = mv_skip[(size_t)t * (CSKIP * MVD) + lane];
        sSC[tl * SC_STRIDE + lane]       = sacc * invd;
        sSC[tl * SC_STRIDE + 32 + lane]  = sc_skip[(size_t)t * SSC + lane];
    }
    __syncwarp();

    // ---------------- Phase 2: mv output (fused Weff), half-warp x 2 targets -
    {
        const int q   = (tid >> 4) & 1;           // half-warp
        const int sub = tid & 15;                 // blade index
        const int tlA = warp * 4 + 2 * q;
        const int tlB = tlA + 1;
        const float* mA = sMV + tlA * MV_STRIDE + sub;
        const float* mB = sMV + tlB * MV_STRIDE + sub;
        float oa[16], ob[16];
        #pragma unroll
        for (int c = 0; c < 16; c++) { oa[c] = 0.f; ob[c] = 0.f; }
        #pragma unroll
        for (int cp = 0; cp < CCH + CSKIP; cp++) {
            const float ma = mA[cp * 16];
            const float mb = mB[cp * 16];
            const float4* wr = (const float4*)(g_Weff + cp * 16);
            float4 w0 = __ldg(wr), w1 = __ldg(wr + 1), w2 = __ldg(wr + 2), w3 = __ldg(wr + 3);
            oa[0]  = fmaf(ma, w0.x, oa[0]);  ob[0]  = fmaf(mb, w0.x, ob[0]);
            oa[1]  = fmaf(ma, w0.y, oa[1]);  ob[1]  = fmaf(mb, w0.y, ob[1]);
            oa[2]  = fmaf(ma, w0.z, oa[2]);  ob[2]  = fmaf(mb, w0.z, ob[2]);
            oa[3]  = fmaf(ma, w0.w, oa[3]);  ob[3]  = fmaf(mb, w0.w, ob[3]);
            oa[4]  = fmaf(ma, w1.x, oa[4]);  ob[4]  = fmaf(mb, w1.x, ob[4]);
            oa[5]  = fmaf(ma, w1.y, oa[5]);  ob[5]  = fmaf(mb, w1.y, ob[5]);
            oa[6]  = fmaf(ma, w1.z, oa[6]);  ob[6]  = fmaf(mb, w1.z, ob[6]);
            oa[7]  = fmaf(ma, w1.w, oa[7]);  ob[7]  = fmaf(mb, w1.w, ob[7]);
            oa[8]  = fmaf(ma, w2.x, oa[8]);  ob[8]  = fmaf(mb, w2.x, ob[8]);
            oa[9]  = fmaf(ma, w2.y, oa[9]);  ob[9]  = fmaf(mb, w2.y, ob[9]);
            oa[10] = fmaf(ma, w2.z, oa[10]); ob[10] = fmaf(mb, w2.z, ob[10]);
            oa[11] = fmaf(ma, w2.w, oa[11]); ob[11] = fmaf(mb, w2.w, ob[11]);
            oa[12] = fmaf(ma, w3.x, oa[12]); ob[12] = fmaf(mb, w3.x, ob[12]);
            oa[13] = fmaf(ma, w3.y, oa[13]); ob[13] = fmaf(mb, w3.y, ob[13]);
            oa[14] = fmaf(ma, w3.z, oa[14]); ob[14] = fmaf(mb, w3.z, ob[14]);
            oa[15] = fmaf(ma, w3.w, oa[15]); ob[15] = fmaf(mb, w3.w, ob[15]);
        }
        float* dA = out_mv + (size_t)(tbase + tlA) * ROW_MV + sub;
        float* dB = out_mv + (size_t)(tbase + tlB) * ROW_MV + sub;
        #pragma unroll
        for (int c = 0; c < 16; c++) { dA[c * 16] = oa[c]; dB[c * 16] = ob[c]; }
    }

    // ---------------- Phase 3a: scalar hidden + gelu --------------------------
    // warp = 4 targets {4w..4w+3}; lane = h-pair (h = 2*lane, 2*lane+1)
    {
        const int r0 = warp * 4;
        float2 bb = __ldg((const float2*)(b1_s + 2 * lane));
        float a0x = bb.x, a0y = bb.y;   // target r0
        float a1x = bb.x, a1y = bb.y;   // target r0+1
        float a2x = bb.x, a2y = bb.y;   // target r0+2
        float a3x = bb.x, a3y = bb.y;   // target r0+3
        const float* x0 = sSC + (r0 + 0) * SC_STRIDE;
        const float* x1 = sSC + (r0 + 1) * SC_STRIDE;
        const float* x2 = sSC + (r0 + 2) * SC_STRIDE;
        const float* x3 = sSC + (r0 + 3) * SC_STRIDE;
        #pragma unroll
        for (int jc = 0; jc < 16; jc++) {
            float4 v0 = *(const float4*)(x0 + 4 * jc);   // broadcast
            float4 v1 = *(const float4*)(x1 + 4 * jc);
            float4 v2 = *(const float4*)(x2 + 4 * jc);
            float4 v3 = *(const float4*)(x3 + 4 * jc);
            #pragma unroll
            for (int r = 0; r < 4; r++) {
                const int j = 4 * jc + r;
                float2 wv = __ldg((const float2*)(W1_s + j * HID + 2 * lane));
                const float e0 = (r == 0) ? v0.x : (r == 1) ? v0.y : (r == 2) ? v0.z : v0.w;
                const float e1 = (r == 0) ? v1.x : (r == 1) ? v1.y : (r == 2) ? v1.z : v1.w;
                const float e2 = (r == 0) ? v2.x : (r == 1) ? v2.y : (r == 2) ? v2.z : v2.w;
                const float e3 = (r == 0) ? v3.x : (r == 1) ? v3.y : (r == 2) ? v3.z : v3.w;
                a0x = fmaf(e0, wv.x, a0x); a0y = fmaf(e0, wv.y, a0y);
                a1x = fmaf(e1, wv.x, a1x); a1y = fmaf(e1, wv.y, a1y);
                a2x = fmaf(e2, wv.x, a2x); a2y = fmaf(e2, wv.y, a2y);
                a3x = fmaf(e3, wv.x, a3x); a3y = fmaf(e3, wv.y, a3y);
            }
        }
        __syncwarp();   // all x reads done before in-place h writes
        *(float2*)(sSC + (r0 + 0) * SC_STRIDE + 2 * lane) = make_float2(gelu_tanh(a0x), gelu_tanh(a0y));
        *(float2*)(sSC + (r0 + 1) * SC_STRIDE + 2 * lane) = make_float2(gelu_tanh(a1x), gelu_tanh(a1y));
        *(float2*)(sSC + (r0 + 2) * SC_STRIDE + 2 * lane) = make_float2(gelu_tanh(a2x), gelu_tanh(a2y));
        *(float2*)(sSC + (r0 + 3) * SC_STRIDE + 2 * lane) = make_float2(gelu_tanh(a3x), gelu_tanh(a3y));
    }
    __syncwarp();

    // ---------------- Phase 3b: scalar output ---------------------------------
    // warp = 4 targets; lane = output channel (32 channels)
    {
        const int r0 = warp * 4;
        const float bb = __ldg(b2_s + lane);
        float a0 = bb, a1 = bb, a2 = bb, a3 = bb;
        const float* h0 = sSC + (r0 + 0) * SC_STRIDE;
        const float* h1 = sSC + (r0 + 1) * SC_STRIDE;
        const float* h2 = sSC + (r0 + 2) * SC_STRIDE;
        const float* h3 = sSC + (r0 + 3) * SC_STRIDE;
        #pragma unroll
        for (int hc = 0; hc < 16; hc++) {
            float4 v0 = *(const float4*)(h0 + 4 * hc);   // broadcast
            float4 v1 = *(const float4*)(h1 + 4 * hc);
            float4 v2 = *(const float4*)(h2 + 4 * hc);
            float4 v3 = *(const float4*)(h3 + 4 * hc);
            #pragma unroll
            for (int r = 0; r < 4; r++) {
                const int j = 4 * hc + r;
                float wv = __ldg(W2_s + j * SSC + lane);
                const float e0 = (r == 0) ? v0.x : (r == 1) ? v0.y : (r == 2) ? v0.z : v0.w;
                const float e1 = (r == 0) ? v1.x : (r == 1) ? v1.y : (r == 2) ? v1.z : v1.w;
                const float e2 = (r == 0) ? v2.x : (r == 1) ? v2.y : (r == 2) ? v2.z : v2.w;
                const float e3 = (r == 0) ? v3.x : (r == 1) ? v3.y : (r == 2) ? v3.z : v3.w;
                a0 = fmaf(e0, wv, a0);
                a1 = fmaf(e1, wv, a1);
                a2 = fmaf(e2, wv, a2);
                a3 = fmaf(e3, wv, a3);
            }
        }
        out_sc[(size_t)(tbase + r0 + 0) * SSC + lane] = a0;
        out_sc[(size_t)(tbase + r0 + 1) * SSC + lane] = a1;
        out_sc[(size_t)(tbase + r0 + 2) * SSC + lane] = a2;
        out_sc[(size_t)(tbase + r0 + 3) * SSC + lane] = a3;
    }
}

// ---------------------------------------------------------------------------
extern "C" void kernel_launch(void* const* d_in, const int* in_sizes, int n_in,
                              void* d_out, int out_size)
{
    const float* mv_src   = (const float*)d_in[0];
    const float* mv_skip  = (const float*)d_in[1];
    const float* sc_src   = (const float*)d_in[2];
    const float* sc_skip  = (const float*)d_in[3];
    const float* pos_src  = (const float*)d_in[4];
    const float* pos_tgt  = (const float*)d_in[5];
    const int*   isrc     = (const int*)d_in[6];
    const float* W1_mv    = (const float*)d_in[8];
    const float* W2_mv    = (const float*)d_in[9];
    const float* W1_s     = (const float*)d_in[10];
    const float* b1_s     = (const float*)d_in[11];
    const float* W2_s     = (const float*)d_in[12];
    const float* b2_s     = (const float*)d_in[13];

    float* out_mv = (float*)d_out;
    float* out_sc = out_mv + (size_t)N_TGT * CCH * MVD;

    prep_weff<<<1, 288>>>(W1_mv, W2_mv);
    fused_kernel<<<N_TGT / TGT_PER_BLOCK, TPB>>>(
        mv_src, mv_skip, sc_src, sc_skip, pos_src, pos_tgt, isrc,
        W1_s, b1_s, W2_s, b2_s, out_mv, out_sc);
}